// round 15
// baseline (speedup 1.0000x reference)
#include <cuda_runtime.h>
#include <cuda_fp16.h>
#include <cstdint>

#define NN 50000
#define EE 800000
#define HH 64
#define CC 10
#define CAP 96      // bucket capacity per dst row (max in-degree ~42)
#define GRIDN 391   // ceil(NN/128); also edge slices of 2048

#define SW 72
#define WLS 24
#define OFF_H 0
#define OFF_L 18432
#define OFF_W20 36864
#define OFF_W21 46080
#define OFF_WLP 55296
#define SMEM_SZ 58368

// Scratch (allocation-free __device__ globals; zero-init at load).
// degi is parity double-buffered by epoch: gather reads arbitrary src rows,
// so same-launch reset would race; the tail resets the OTHER parity.
__device__ int g_degi[2][NN];
__device__ int g_cnt[NN];               // in-degree/bucket level (tail-reset own rows)
__device__ int g_srcs[NN * CAP];        // bucketed src indices
__device__ __align__(16) __half g_h16[NN * HH];
__device__ unsigned g_start;            // epoch counter (monotonic)
__device__ unsigned g_arrive;           // grid-sync counter (monotonic)

// ---------------------------------------------------------------------------
__device__ __forceinline__ void ldsm_x4(uint32_t& r0, uint32_t& r1, uint32_t& r2,
                                        uint32_t& r3, uint32_t addr) {
    asm volatile("ldmatrix.sync.aligned.m8n8.x4.shared.b16 {%0,%1,%2,%3}, [%4];"
                 : "=r"(r0), "=r"(r1), "=r"(r2), "=r"(r3) : "r"(addr));
}
__device__ __forceinline__ void ldsm_x4_t(uint32_t& r0, uint32_t& r1, uint32_t& r2,
                                          uint32_t& r3, uint32_t addr) {
    asm volatile("ldmatrix.sync.aligned.m8n8.x4.trans.shared.b16 {%0,%1,%2,%3}, [%4];"
                 : "=r"(r0), "=r"(r1), "=r"(r2), "=r"(r3) : "r"(addr));
}
__device__ __forceinline__ void mma16816(float* c, uint32_t a0, uint32_t a1,
                                         uint32_t a2, uint32_t a3,
                                         uint32_t b0, uint32_t b1) {
    asm volatile(
        "mma.sync.aligned.m16n8k16.row.col.f32.f16.f16.f32 "
        "{%0,%1,%2,%3}, {%4,%5,%6,%7}, {%8,%9}, {%0,%1,%2,%3};"
        : "+f"(c[0]), "+f"(c[1]), "+f"(c[2]), "+f"(c[3])
        : "r"(a0), "r"(a1), "r"(a2), "r"(a3), "r"(b0), "r"(b1));
}

// ---------------------------------------------------------------------------
// ONE persistent kernel: gemm1 + fill (pipelined) | gridsync | gather->smem
// + dual MMA + logits MMA + softmax. 391 blocks, 1 wave at 3 blocks/SM.
// ---------------------------------------------------------------------------
__global__ __launch_bounds__(256, 3) void k_fused(
    const float* __restrict__ x,   const float* __restrict__ W1,
    const float* __restrict__ b1,  const float* __restrict__ W20,
    const float* __restrict__ W21, const float* __restrict__ b2,
    const float* __restrict__ Wl,  const float* __restrict__ bl,
    const int* __restrict__ ei,    float* __restrict__ out)
{
    extern __shared__ char dsm[];
    __half* Hs   = (__half*)(dsm + OFF_H);     // x tile, then h tile
    __half* Ls   = (__half*)(dsm + OFF_L);     // lap tile (gathered), then s
    __half* W20s = (__half*)(dsm + OFF_W20);   // W1 in phase 1, W20 in phase 2
    __half* W21s = (__half*)(dsm + OFF_W21);
    __half* Wlp  = (__half*)(dsm + OFF_WLP);
    __shared__ int s_st;
    __shared__ unsigned s_par;

    int tid = threadIdx.x;
    int rowbase = blockIdx.x * 128;

    // epoch parity + dtype detect
    if (tid == 0) s_par = (atomicAdd(&g_start, 1u) / GRIDN) & 1u;
    if (tid < 32) {
        int bad = (ei[2 * tid + 1] != 0);
        unsigned b = __ballot_sync(0xffffffffu, bad);
        if (tid == 0) s_st = b ? 1 : 2;
    }

    // x tile (f32 -> fp16 smem)
#pragma unroll
    for (int j = 0; j < 8; j++) {
        int idx = j * 256 + tid;          // float4 index 0..2047
        int r = idx >> 4;
        int kq = (idx & 15) << 2;
        int grow = rowbase + r;
        float4 v = make_float4(0.f, 0.f, 0.f, 0.f);
        if (grow < NN) v = *(const float4*)&x[grow * HH + kq];
        __half2 p0 = __floats2half2_rn(v.x, v.y);
        __half2 p1 = __floats2half2_rn(v.z, v.w);
        uint2 pk;
        pk.x = *(unsigned*)&p0;
        pk.y = *(unsigned*)&p1;
        *(uint2*)&Hs[r * SW + kq] = pk;
    }
    // W1 (f32 -> fp16, lives in the W20 region during phase 1)
    for (int i = tid; i < HH * HH; i += 256) {
        int k = i >> 6, n = i & 63;
        W20s[k * SW + n] = __float2half(W1[i]);
    }
    __syncthreads();
    int st = s_st;
    unsigned par = s_par;

    // edge loads + atomics (returns in flight during the MMA below)
    int es[8], ed[8], epos[8];
    int ebase = blockIdx.x * 2048 + tid;
#pragma unroll
    for (int j = 0; j < 8; j++) {
        int e = ebase + j * 256;
        if (e < EE) {
            es[j] = __ldg(&ei[e * st]);
            ed[j] = __ldg(&ei[(EE + e) * st]);
        } else { es[j] = -1; ed[j] = 0; }
    }
#pragma unroll
    for (int j = 0; j < 8; j++)
        if (es[j] >= 0) epos[j] = atomicAdd(&g_cnt[ed[j]], 1);
#pragma unroll
    for (int j = 0; j < 8; j++)
        if (es[j] >= 0) atomicAdd(&g_degi[par][es[j]], 1);

    // lane geometry (shared by all MMA passes)
    int warp = tid >> 5, lane = tid & 31;
    int R0 = warp * 16;
    uint32_t sb = (uint32_t)__cvta_generic_to_shared(dsm);
    int cq = 2 * (lane & 3);
    int rr = lane >> 2;
    int ar = R0 + (lane & 15);
    int ac = (lane >> 4) << 3;
    int br = ((lane >> 3) & 1) * 8 + (lane & 7);
    int bc = (lane >> 4) << 3;

    // GEMM1: h = relu(x@W1+b1) -> Hs (own warp rows) + g_h16
    {
        float acc[8][4];
#pragma unroll
        for (int q = 0; q < 8; q++) {
            float bb0 = __ldg(&b1[q * 8 + cq]);
            float bb1 = __ldg(&b1[q * 8 + cq + 1]);
            acc[q][0] = bb0; acc[q][1] = bb1; acc[q][2] = bb0; acc[q][3] = bb1;
        }
#pragma unroll
        for (int ki = 0; ki < 4; ki++) {
            int k0 = ki * 16;
            uint32_t a0, a1, a2, a3;
            ldsm_x4(a0, a1, a2, a3, sb + OFF_H + (ar * SW + k0 + ac) * 2);
#pragma unroll
            for (int p = 0; p < 4; p++) {
                int n0 = p * 16;
                uint32_t w0, w1, w2, w3;
                ldsm_x4_t(w0, w1, w2, w3, sb + OFF_W20 + ((k0 + br) * SW + n0 + bc) * 2);
                mma16816(acc[2 * p],     a0, a1, a2, a3, w0, w1);
                mma16816(acc[2 * p + 1], a0, a1, a2, a3, w2, w3);
            }
        }
#pragma unroll
        for (int q = 0; q < 8; q++) {
            int c = q * 8 + cq;
            __half2 s0 = __floats2half2_rn(fmaxf(acc[q][0], 0.f), fmaxf(acc[q][1], 0.f));
            __half2 s1 = __floats2half2_rn(fmaxf(acc[q][2], 0.f), fmaxf(acc[q][3], 0.f));
            *(__half2*)&Hs[(R0 + rr) * SW + c] = s0;
            *(__half2*)&Hs[(R0 + rr + 8) * SW + c] = s1;
        }
        __syncwarp();
#pragma unroll
        for (int j = 0; j < 4; j++) {
            int i = j * 32 + lane;
            int rl = R0 + (i >> 3);
            int c8 = (i & 7) * 8;
            int grow = rowbase + rl;
            if (grow < NN)
                *(uint4*)&g_h16[grow * HH + c8] = *(uint4*)&Hs[rl * SW + c8];
        }
    }

    // srcs stores (atomic returns resolved by now)
#pragma unroll
    for (int j = 0; j < 8; j++)
        if (es[j] >= 0 && epos[j] < CAP) g_srcs[ed[j] * CAP + epos[j]] = es[j];

    // ---- grid sync (391 blocks, single wave, monotonic counter) ----
    __threadfence();
    __syncthreads();
    if (tid == 0) {
        unsigned old = atomicAdd(&g_arrive, 1u);
        unsigned tgt = (old / GRIDN) * GRIDN + GRIDN;
        while (*(volatile unsigned*)&g_arrive < tgt) __nanosleep(64);
    }
    __syncthreads();
    __threadfence();

    // ---- phase 2: weights + gather own rows into Ls ----
    for (int i = tid; i < HH * HH; i += 256) {
        int k = i >> 6, n = i & 63;
        W20s[k * SW + n] = __float2half(W20[i]);
        W21s[k * SW + n] = __float2half(W21[i]);
    }
    for (int i = tid; i < HH * 16; i += 256) {
        int k = i >> 4, c = i & 15;
        Wlp[k * WLS + c] = (c < CC) ? __float2half(__ldg(&Wl[k * CC + c]))
                                    : __float2half(0.f);
    }

    {
        int g = tid >> 3, l = tid & 7;
        unsigned gmask = 0xffu << (tid & 24);
#pragma unroll 1
        for (int p2 = 0; p2 < 4; p2++) {
            int rl = p2 * 32 + g;
            int row = rowbase + rl;
            int len = 0, start = 0;
            if (row < NN) { len = min(g_cnt[row], CAP); start = row * CAP; }
            float a0 = 0.f, a1 = 0.f, a2 = 0.f, a3 = 0.f;
            float a4 = 0.f, a5 = 0.f, a6 = 0.f, a7 = 0.f;
            for (int base = 0; base < len; base += 8) {
                int j = base + l;
                int sV = 0;
                float w = 0.f;
                if (j < len) {
                    sV = __ldg(&g_srcs[start + j]);
                    int dg = __ldg(&g_degi[par][sV]);
                    w = (dg > 0) ? rsqrtf((float)dg) : 0.f;
                }
                int m = min(8, len - base);
#pragma unroll 4
                for (int jj = 0; jj < m; jj++) {
                    int sj = __shfl_sync(gmask, sV, jj, 8);
                    float wj = __shfl_sync(gmask, w, jj, 8);
                    uint4 u = __ldg((const uint4*)&g_h16[sj * HH + l * 8]);
                    float2 f0 = __half22float2(*(__half2*)&u.x);
                    float2 f1 = __half22float2(*(__half2*)&u.y);
                    float2 f2 = __half22float2(*(__half2*)&u.z);
                    float2 f3 = __half22float2(*(__half2*)&u.w);
                    a0 = fmaf(wj, f0.x, a0); a1 = fmaf(wj, f0.y, a1);
                    a2 = fmaf(wj, f1.x, a2); a3 = fmaf(wj, f1.y, a3);
                    a4 = fmaf(wj, f2.x, a4); a5 = fmaf(wj, f2.y, a5);
                    a6 = fmaf(wj, f3.x, a6); a7 = fmaf(wj, f3.y, a7);
                }
            }
            uint4 ov = make_uint4(0u, 0u, 0u, 0u);
            if (row < NN) {
                int dgr = __ldg(&g_degi[par][row]);
                float sc = (dgr > 0) ? -rsqrtf((float)dgr) : 0.f;
                __half2 o0 = __floats2half2_rn(a0 * sc, a1 * sc);
                __half2 o1 = __floats2half2_rn(a2 * sc, a3 * sc);
                __half2 o2 = __floats2half2_rn(a4 * sc, a5 * sc);
                __half2 o3 = __floats2half2_rn(a6 * sc, a7 * sc);
                ov.x = *(unsigned*)&o0; ov.y = *(unsigned*)&o1;
                ov.z = *(unsigned*)&o2; ov.w = *(unsigned*)&o3;
            }
            *(uint4*)&Ls[rl * SW + l * 8] = ov;
        }
    }
    __syncthreads();

    // ---- dual MMA: acc = h@W20 + lap@W21 + b2 ----
    float acc[8][4];
#pragma unroll
    for (int q = 0; q < 8; q++) {
        float bb0 = __ldg(&b2[q * 8 + cq]);
        float bb1 = __ldg(&b2[q * 8 + cq + 1]);
        acc[q][0] = bb0; acc[q][1] = bb1; acc[q][2] = bb0; acc[q][3] = bb1;
    }
#pragma unroll
    for (int ki = 0; ki < 4; ki++) {
        int k0 = ki * 16;
        uint32_t ha0, ha1, ha2, ha3, la0, la1, la2, la3;
        ldsm_x4(ha0, ha1, ha2, ha3, sb + OFF_H + (ar * SW + k0 + ac) * 2);
        ldsm_x4(la0, la1, la2, la3, sb + OFF_L + (ar * SW + k0 + ac) * 2);
#pragma unroll
        for (int p = 0; p < 4; p++) {
            int n0 = p * 16;
            uint32_t w0, w1, w2, w3;
            ldsm_x4_t(w0, w1, w2, w3, sb + OFF_W20 + ((k0 + br) * SW + n0 + bc) * 2);
            mma16816(acc[2 * p],     ha0, ha1, ha2, ha3, w0, w1);
            mma16816(acc[2 * p + 1], ha0, ha1, ha2, ha3, w2, w3);
            uint32_t v0, v1, v2, v3;
            ldsm_x4_t(v0, v1, v2, v3, sb + OFF_W21 + ((k0 + br) * SW + n0 + bc) * 2);
            mma16816(acc[2 * p],     la0, la1, la2, la3, v0, v1);
            mma16816(acc[2 * p + 1], la0, la1, la2, la3, v2, v3);
        }
    }

    // s = relu(acc) + h -> Ls (own warp rows only)
#pragma unroll
    for (int q = 0; q < 8; q++) {
        int c = q * 8 + cq;
        float2 h0 = __half22float2(*(__half2*)&Hs[(R0 + rr) * SW + c]);
        float2 h1 = __half22float2(*(__half2*)&Hs[(R0 + rr + 8) * SW + c]);
        __half2 s0 = __floats2half2_rn(fmaxf(acc[q][0], 0.f) + h0.x,
                                       fmaxf(acc[q][1], 0.f) + h0.y);
        __half2 s1 = __floats2half2_rn(fmaxf(acc[q][2], 0.f) + h1.x,
                                       fmaxf(acc[q][3], 0.f) + h1.y);
        *(__half2*)&Ls[(R0 + rr) * SW + c] = s0;
        *(__half2*)&Ls[(R0 + rr + 8) * SW + c] = s1;
    }
    __syncwarp();

    // logits MMA: acc2 = s @ Wlp
    float acc2[2][4];
#pragma unroll
    for (int p = 0; p < 2; p++) {
        acc2[p][0] = 0.f; acc2[p][1] = 0.f; acc2[p][2] = 0.f; acc2[p][3] = 0.f;
    }
#pragma unroll
    for (int ki = 0; ki < 4; ki++) {
        int k0 = ki * 16;
        uint32_t sa0, sa1, sa2, sa3;
        ldsm_x4(sa0, sa1, sa2, sa3, sb + OFF_L + (ar * SW + k0 + ac) * 2);
        uint32_t u0, u1, u2, u3;
        ldsm_x4_t(u0, u1, u2, u3, sb + OFF_WLP + ((k0 + br) * WLS + bc) * 2);
        mma16816(acc2[0], sa0, sa1, sa2, sa3, u0, u1);
        mma16816(acc2[1], sa0, sa1, sa2, sa3, u2, u3);
    }

    // softmax over quad
    float bl0 = __ldg(&bl[cq]);
    float bl1 = __ldg(&bl[cq + 1]);
    float bl8 = (cq == 0) ? __ldg(&bl[8]) : 0.f;
    float bl9 = (cq == 0) ? __ldg(&bl[9]) : 0.f;
#pragma unroll
    for (int hsel = 0; hsel < 2; hsel++) {
        float v0 = acc2[0][2 * hsel]     + bl0;
        float v1 = acc2[0][2 * hsel + 1] + bl1;
        float v2 = (cq == 0) ? acc2[1][2 * hsel]     + bl8 : -1e30f;
        float v3 = (cq == 0) ? acc2[1][2 * hsel + 1] + bl9 : -1e30f;

        float m = fmaxf(fmaxf(v0, v1), fmaxf(v2, v3));
        m = fmaxf(m, __shfl_xor_sync(0xffffffffu, m, 1));
        m = fmaxf(m, __shfl_xor_sync(0xffffffffu, m, 2));

        float sum = expf(v0 - m) + expf(v1 - m);
        if (cq == 0) sum += expf(v2 - m) + expf(v3 - m);
        sum += __shfl_xor_sync(0xffffffffu, sum, 1);
        sum += __shfl_xor_sync(0xffffffffu, sum, 2);
        float lse = m + logf(sum);

        int row = rowbase + R0 + rr + hsel * 8;
        if (row < NN) {
            out[row * CC + cq]     = v0 - lse;
            out[row * CC + cq + 1] = v1 - lse;
            if (cq == 0) {
                out[row * CC + 8] = v2 - lse;
                out[row * CC + 9] = v3 - lse;
            }
        }
    }

    // Tail: reset cnt (own rows) and the OTHER degi parity for next run
    if (tid < 128) {
        int row = rowbase + tid;
        if (row < NN) g_cnt[row] = 0;
    }
    for (int i = blockIdx.x * 256 + tid; i < NN; i += GRIDN * 256)
        g_degi[par ^ 1u][i] = 0;
}

// ---------------------------------------------------------------------------
extern "C" void kernel_launch(void* const* d_in, const int* in_sizes, int n_in,
                              void* d_out, int out_size) {
    const float* x   = (const float*)d_in[0];
    const int*   ei  = (const int*)d_in[1];
    const float* W1  = (const float*)d_in[2];
    const float* b1  = (const float*)d_in[3];
    const float* W20 = (const float*)d_in[4];
    const float* W21 = (const float*)d_in[5];
    const float* b2  = (const float*)d_in[6];
    const float* Wl  = (const float*)d_in[7];
    const float* bl  = (const float*)d_in[8];
    float* out = (float*)d_out;

    static int init_done = 0;
    if (!init_done) {
        cudaFuncSetAttribute(k_fused, cudaFuncAttributeMaxDynamicSharedMemorySize, SMEM_SZ);
        init_done = 1;
    }

    k_fused<<<GRIDN, 256, SMEM_SZ>>>(x, W1, b1, W20, W21, b2, Wl, bl, ei, out);
}

// round 16
// speedup vs baseline: 1.0779x; 1.0779x over previous
#include <cuda_runtime.h>
#include <cuda_fp16.h>
#include <cstdint>

#define NN 50000
#define EE 800000
#define HH 64
#define CC 10
#define CAP 96      // bucket capacity per dst row (max in-degree ~42)
#define GRIDN 391   // ceil(NN/128) = ceil(EE/2048)

// Scratch (allocation-free __device__ globals; zero-init at load).
// degi parity double-buffered: k_gf2 reads arbitrary src degi while its tail
// resets — so it resets the OTHER parity. Epoch counters are monotonic.
__device__ int g_degi[2][NN];
__device__ int g_cnt[NN];
__device__ int g_srcs[NN * CAP];
__device__ __align__(16) __half g_h16[NN * HH];
__device__ unsigned g_epA;   // k_fill epoch
__device__ unsigned g_epB;   // k_gf2 epoch

// ---------------------------------------------------------------------------
__device__ __forceinline__ void ldsm_x4(uint32_t& r0, uint32_t& r1, uint32_t& r2,
                                        uint32_t& r3, uint32_t addr) {
    asm volatile("ldmatrix.sync.aligned.m8n8.x4.shared.b16 {%0,%1,%2,%3}, [%4];"
                 : "=r"(r0), "=r"(r1), "=r"(r2), "=r"(r3) : "r"(addr));
}
__device__ __forceinline__ void ldsm_x4_t(uint32_t& r0, uint32_t& r1, uint32_t& r2,
                                          uint32_t& r3, uint32_t addr) {
    asm volatile("ldmatrix.sync.aligned.m8n8.x4.trans.shared.b16 {%0,%1,%2,%3}, [%4];"
                 : "=r"(r0), "=r"(r1), "=r"(r2), "=r"(r3) : "r"(addr));
}
__device__ __forceinline__ void mma16816(float* c, uint32_t a0, uint32_t a1,
                                         uint32_t a2, uint32_t a3,
                                         uint32_t b0, uint32_t b1) {
    asm volatile(
        "mma.sync.aligned.m16n8k16.row.col.f32.f16.f16.f32 "
        "{%0,%1,%2,%3}, {%4,%5,%6,%7}, {%8,%9}, {%0,%1,%2,%3};"
        : "+f"(c[0]), "+f"(c[1]), "+f"(c[2]), "+f"(c[3])
        : "r"(a0), "r"(a1), "r"(a2), "r"(a3), "r"(b0), "r"(b1));
}

// ---------------------------------------------------------------------------
// A0: fused hist + bucket fill (single edge pass). 4 edges/thread ILP.
// Writes degi[par] selected by its own epoch counter.
// ---------------------------------------------------------------------------
__global__ __launch_bounds__(512) void k_fill(const int* __restrict__ ei) {
    __shared__ int s_st;
    __shared__ unsigned s_par;
    if (threadIdx.x == 0) s_par = (atomicAdd(&g_epA, 1u) / GRIDN) & 1u;
    if (threadIdx.x < 32) {
        int bad = (ei[2 * threadIdx.x + 1] != 0);
        unsigned b = __ballot_sync(0xffffffffu, bad);
        if (threadIdx.x == 0) s_st = b ? 1 : 2;
    }
    __syncthreads();
    int st = s_st;
    unsigned par = s_par;

    int base = blockIdx.x * 2048 + threadIdx.x;
    int s[4], d[4], pos[4];
#pragma unroll
    for (int j = 0; j < 4; j++) {
        int e = base + j * 512;
        if (e < EE) {
            s[j] = __ldg(&ei[e * st]);
            d[j] = __ldg(&ei[(EE + e) * st]);
        } else { s[j] = -1; d[j] = 0; }
    }
#pragma unroll
    for (int j = 0; j < 4; j++)
        if (s[j] >= 0) pos[j] = atomicAdd(&g_cnt[d[j]], 1);
#pragma unroll
    for (int j = 0; j < 4; j++)
        if (s[j] >= 0) {
            if (pos[j] < CAP) g_srcs[d[j] * CAP + pos[j]] = s[j];
            atomicAdd(&g_degi[par][s[j]], 1);
        }
}

// ---------------------------------------------------------------------------
// B0 (concurrent stream): HMMA GEMM1  h16 = fp16(relu(x@W1+b1))
// ---------------------------------------------------------------------------
#define G1_SW 72
#define G1_OFF_X 0
#define G1_OFF_W 18432
#define G1_SMEM 27648

__global__ __launch_bounds__(256) void k_gemm1(const float* __restrict__ x,
                                               const float* __restrict__ W1,
                                               const float* __restrict__ b1) {
    extern __shared__ char g1sm[];
    __half* Xs = (__half*)(g1sm + G1_OFF_X);
    __half* Ws = (__half*)(g1sm + G1_OFF_W);

    int tid = threadIdx.x;
    int rowbase = blockIdx.x * 128;

#pragma unroll
    for (int j = 0; j < 8; j++) {
        int idx = j * 256 + tid;
        int r = idx >> 4;
        int kq = (idx & 15) << 2;
        int grow = rowbase + r;
        float4 v = make_float4(0.f, 0.f, 0.f, 0.f);
        if (grow < NN) v = *(const float4*)&x[grow * HH + kq];
        __half2 p0 = __floats2half2_rn(v.x, v.y);
        __half2 p1 = __floats2half2_rn(v.z, v.w);
        uint2 pk;
        pk.x = *(unsigned*)&p0;
        pk.y = *(unsigned*)&p1;
        *(uint2*)&Xs[r * G1_SW + kq] = pk;
    }
    for (int i = tid; i < HH * HH; i += 256) {
        int k = i >> 6, n = i & 63;
        Ws[k * G1_SW + n] = __float2half(W1[i]);
    }
    __syncthreads();

    int warp = tid >> 5, lane = tid & 31;
    int R0 = warp * 16;
    uint32_t sb = (uint32_t)__cvta_generic_to_shared(g1sm);

    float acc[8][4];
    int cq = 2 * (lane & 3);
    int rr = lane >> 2;
#pragma unroll
    for (int q = 0; q < 8; q++) {
        float bb0 = __ldg(&b1[q * 8 + cq]);
        float bb1 = __ldg(&b1[q * 8 + cq + 1]);
        acc[q][0] = bb0; acc[q][1] = bb1; acc[q][2] = bb0; acc[q][3] = bb1;
    }

    int ar = R0 + (lane & 15);
    int ac = (lane >> 4) << 3;
    int br = ((lane >> 3) & 1) * 8 + (lane & 7);
    int bc = (lane >> 4) << 3;

#pragma unroll
    for (int ki = 0; ki < 4; ki++) {
        int k0 = ki * 16;
        uint32_t a0, a1, a2, a3;
        ldsm_x4(a0, a1, a2, a3, sb + G1_OFF_X + (ar * G1_SW + k0 + ac) * 2);
#pragma unroll
        for (int p = 0; p < 4; p++) {
            int n0 = p * 16;
            uint32_t w0, w1, w2, w3;
            ldsm_x4_t(w0, w1, w2, w3, sb + G1_OFF_W + ((k0 + br) * G1_SW + n0 + bc) * 2);
            mma16816(acc[2 * p],     a0, a1, a2, a3, w0, w1);
            mma16816(acc[2 * p + 1], a0, a1, a2, a3, w2, w3);
        }
    }

#pragma unroll
    for (int q = 0; q < 8; q++) {
        int c = q * 8 + cq;
        __half2 s0 = __floats2half2_rn(fmaxf(acc[q][0], 0.f), fmaxf(acc[q][1], 0.f));
        __half2 s1 = __floats2half2_rn(fmaxf(acc[q][2], 0.f), fmaxf(acc[q][3], 0.f));
        *(__half2*)&Xs[(R0 + rr) * G1_SW + c] = s0;
        *(__half2*)&Xs[(R0 + rr + 8) * G1_SW + c] = s1;
    }
    __syncwarp();

#pragma unroll
    for (int j = 0; j < 4; j++) {
        int i = j * 32 + lane;
        int rl = R0 + (i >> 3);
        int c8 = (i & 7) * 8;
        int grow = rowbase + rl;
        if (grow < NN)
            *(uint4*)&g_h16[grow * HH + c8] = *(uint4*)&Xs[rl * G1_SW + c8];
    }
}

// ---------------------------------------------------------------------------
// A1 (after join): fused gather + dual MMA + logits MMA + softmax.
//   Gather writes lap DIRECTLY into smem Ls (no g_lap16 round-trip).
//   Own-rows-only use of cnt/srcs -> no cross-block coupling, no grid sync.
//   Tail: reset own-row cnt + other-parity degi.
// ---------------------------------------------------------------------------
#define SW 72
#define WLS 24
#define OFF_H 0
#define OFF_L 18432
#define OFF_W20 36864
#define OFF_W21 46080
#define OFF_WLP 55296
#define SMEM_F2 58368

__global__ __launch_bounds__(256) void k_gf2(const float* __restrict__ W20,
                                             const float* __restrict__ W21,
                                             const float* __restrict__ b2,
                                             const float* __restrict__ Wl,
                                             const float* __restrict__ bl,
                                             float* __restrict__ out) {
    extern __shared__ char dsm[];
    __half* Hs   = (__half*)(dsm + OFF_H);
    __half* Ls   = (__half*)(dsm + OFF_L);
    __half* W20s = (__half*)(dsm + OFF_W20);
    __half* W21s = (__half*)(dsm + OFF_W21);
    __half* Wlp  = (__half*)(dsm + OFF_WLP);
    __shared__ unsigned s_par;

    int tid = threadIdx.x;
    int rowbase = blockIdx.x * 128;
    if (tid == 0) s_par = (atomicAdd(&g_epB, 1u) / GRIDN) & 1u;

    // weights
    for (int i = tid; i < HH * HH; i += 256) {
        int k = i >> 6, n = i & 63;
        W20s[k * SW + n] = __float2half(W20[i]);
        W21s[k * SW + n] = __float2half(W21[i]);
    }
    for (int i = tid; i < HH * 16; i += 256) {
        int k = i >> 4, c = i & 15;
        Wlp[k * WLS + c] = (c < CC) ? __float2half(__ldg(&Wl[k * CC + c]))
                                    : __float2half(0.f);
    }
    // h tile
#pragma unroll
    for (int j = 0; j < 4; j++) {
        int idx = j * 256 + tid;           // uint4 index 0..1023
        int r = idx >> 3;
        int c8 = (idx & 7) * 8;
        int grow = rowbase + r;
        uint4 v = make_uint4(0u, 0u, 0u, 0u);
        if (grow < NN) v = __ldg((const uint4*)&g_h16[grow * HH + c8]);
        *(uint4*)&Hs[r * SW + c8] = v;
    }
    __syncthreads();
    unsigned par = s_par;

    // gather own 128 rows -> Ls  (8 lanes/row, 32 rows/pass, 4 passes)
    {
        int g = tid >> 3, l = tid & 7;
        unsigned gmask = 0xffu << (tid & 24);
#pragma unroll 1
        for (int p2 = 0; p2 < 4; p2++) {
            int rl = p2 * 32 + g;
            int row = rowbase + rl;
            int len = 0, start = 0;
            if (row < NN) { len = min(__ldg(&g_cnt[row]), CAP); start = row * CAP; }
            float a0 = 0.f, a1 = 0.f, a2 = 0.f, a3 = 0.f;
            float a4 = 0.f, a5 = 0.f, a6 = 0.f, a7 = 0.f;
            for (int base = 0; base < len; base += 8) {
                int j = base + l;
                int sV = 0;
                float w = 0.f;
                if (j < len) {
                    sV = __ldg(&g_srcs[start + j]);
                    int dg = __ldg(&g_degi[par][sV]);
                    w = (dg > 0) ? rsqrtf((float)dg) : 0.f;
                }
                int m = min(8, len - base);
#pragma unroll 4
                for (int jj = 0; jj < m; jj++) {
                    int sj = __shfl_sync(gmask, sV, jj, 8);
                    float wj = __shfl_sync(gmask, w, jj, 8);
                    uint4 u = __ldg((const uint4*)&g_h16[sj * HH + l * 8]);
                    float2 f0 = __half22float2(*(__half2*)&u.x);
                    float2 f1 = __half22float2(*(__half2*)&u.y);
                    float2 f2 = __half22float2(*(__half2*)&u.z);
                    float2 f3 = __half22float2(*(__half2*)&u.w);
                    a0 = fmaf(wj, f0.x, a0); a1 = fmaf(wj, f0.y, a1);
                    a2 = fmaf(wj, f1.x, a2); a3 = fmaf(wj, f1.y, a3);
                    a4 = fmaf(wj, f2.x, a4); a5 = fmaf(wj, f2.y, a5);
                    a6 = fmaf(wj, f3.x, a6); a7 = fmaf(wj, f3.y, a7);
                }
            }
            uint4 ov = make_uint4(0u, 0u, 0u, 0u);
            if (row < NN) {
                int dgr = __ldg(&g_degi[par][row]);
                float sc = (dgr > 0) ? -rsqrtf((float)dgr) : 0.f;
                __half2 o0 = __floats2half2_rn(a0 * sc, a1 * sc);
                __half2 o1 = __floats2half2_rn(a2 * sc, a3 * sc);
                __half2 o2 = __floats2half2_rn(a4 * sc, a5 * sc);
                __half2 o3 = __floats2half2_rn(a6 * sc, a7 * sc);
                ov.x = *(unsigned*)&o0; ov.y = *(unsigned*)&o1;
                ov.z = *(unsigned*)&o2; ov.w = *(unsigned*)&o3;
            }
            *(uint4*)&Ls[rl * SW + l * 8] = ov;
        }
    }
    __syncthreads();

    int warp = tid >> 5, lane = tid & 31;
    int R0 = warp * 16;
    uint32_t sb = (uint32_t)__cvta_generic_to_shared(dsm);

    float acc[8][4];
    int cq = 2 * (lane & 3);
    int rr = lane >> 2;
#pragma unroll
    for (int q = 0; q < 8; q++) {
        float bb0 = __ldg(&b2[q * 8 + cq]);
        float bb1 = __ldg(&b2[q * 8 + cq + 1]);
        acc[q][0] = bb0; acc[q][1] = bb1; acc[q][2] = bb0; acc[q][3] = bb1;
    }

    int ar = R0 + (lane & 15);
    int ac = (lane >> 4) << 3;
    int br = ((lane >> 3) & 1) * 8 + (lane & 7);
    int bc = (lane >> 4) << 3;

#pragma unroll
    for (int ki = 0; ki < 4; ki++) {
        int k0 = ki * 16;
        uint32_t ha0, ha1, ha2, ha3, la0, la1, la2, la3;
        ldsm_x4(ha0, ha1, ha2, ha3, sb + OFF_H + (ar * SW + k0 + ac) * 2);
        ldsm_x4(la0, la1, la2, la3, sb + OFF_L + (ar * SW + k0 + ac) * 2);
#pragma unroll
        for (int p = 0; p < 4; p++) {
            int n0 = p * 16;
            uint32_t w0, w1, w2, w3;
            ldsm_x4_t(w0, w1, w2, w3, sb + OFF_W20 + ((k0 + br) * SW + n0 + bc) * 2);
            mma16816(acc[2 * p],     ha0, ha1, ha2, ha3, w0, w1);
            mma16816(acc[2 * p + 1], ha0, ha1, ha2, ha3, w2, w3);
            uint32_t v0, v1, v2, v3;
            ldsm_x4_t(v0, v1, v2, v3, sb + OFF_W21 + ((k0 + br) * SW + n0 + bc) * 2);
            mma16816(acc[2 * p],     la0, la1, la2, la3, v0, v1);
            mma16816(acc[2 * p + 1], la0, la1, la2, la3, v2, v3);
        }
    }

    // s = relu(acc) + h -> Ls (own warp rows only)
#pragma unroll
    for (int q = 0; q < 8; q++) {
        int c = q * 8 + cq;
        float2 h0 = __half22float2(*(__half2*)&Hs[(R0 + rr) * SW + c]);
        float2 h1 = __half22float2(*(__half2*)&Hs[(R0 + rr + 8) * SW + c]);
        __half2 s0 = __floats2half2_rn(fmaxf(acc[q][0], 0.f) + h0.x,
                                       fmaxf(acc[q][1], 0.f) + h0.y);
        __half2 s1 = __floats2half2_rn(fmaxf(acc[q][2], 0.f) + h1.x,
                                       fmaxf(acc[q][3], 0.f) + h1.y);
        *(__half2*)&Ls[(R0 + rr) * SW + c] = s0;
        *(__half2*)&Ls[(R0 + rr + 8) * SW + c] = s1;
    }
    __syncwarp();

    // logits MMA
    float acc2[2][4];
#pragma unroll
    for (int p = 0; p < 2; p++) {
        acc2[p][0] = 0.f; acc2[p][1] = 0.f; acc2[p][2] = 0.f; acc2[p][3] = 0.f;
    }
#pragma unroll
    for (int ki = 0; ki < 4; ki++) {
        int k0 = ki * 16;
        uint32_t sa0, sa1, sa2, sa3;
        ldsm_x4(sa0, sa1, sa2, sa3, sb + OFF_L + (ar * SW + k0 + ac) * 2);
        uint32_t u0, u1, u2, u3;
        ldsm_x4_t(u0, u1, u2, u3, sb + OFF_WLP + ((k0 + br) * WLS + bc) * 2);
        mma16816(acc2[0], sa0, sa1, sa2, sa3, u0, u1);
        mma16816(acc2[1], sa0, sa1, sa2, sa3, u2, u3);
    }

    // softmax over quad
    float bl0 = __ldg(&bl[cq]);
    float bl1 = __ldg(&bl[cq + 1]);
    float bl8 = (cq == 0) ? __ldg(&bl[8]) : 0.f;
    float bl9 = (cq == 0) ? __ldg(&bl[9]) : 0.f;
#pragma unroll
    for (int hsel = 0; hsel < 2; hsel++) {
        float v0 = acc2[0][2 * hsel]     + bl0;
        float v1 = acc2[0][2 * hsel + 1] + bl1;
        float v2 = (cq == 0) ? acc2[1][2 * hsel]     + bl8 : -1e30f;
        float v3 = (cq == 0) ? acc2[1][2 * hsel + 1] + bl9 : -1e30f;

        float m = fmaxf(fmaxf(v0, v1), fmaxf(v2, v3));
        m = fmaxf(m, __shfl_xor_sync(0xffffffffu, m, 1));
        m = fmaxf(m, __shfl_xor_sync(0xffffffffu, m, 2));

        float sum = expf(v0 - m) + expf(v1 - m);
        if (cq == 0) sum += expf(v2 - m) + expf(v3 - m);
        sum += __shfl_xor_sync(0xffffffffu, sum, 1);
        sum += __shfl_xor_sync(0xffffffffu, sum, 2);
        float lse = m + logf(sum);

        int row = rowbase + R0 + rr + hsel * 8;
        if (row < NN) {
            out[row * CC + cq]     = v0 - lse;
            out[row * CC + cq + 1] = v1 - lse;
            if (cq == 0) {
                out[row * CC + 8] = v2 - lse;
                out[row * CC + 9] = v3 - lse;
            }
        }
    }

    // Tail: reset own-row cnt + OTHER-parity degi
    if (tid < 128) {
        int row = rowbase + tid;
        if (row < NN) g_cnt[row] = 0;
    }
    for (int i = blockIdx.x * 256 + tid; i < NN; i += GRIDN * 256)
        g_degi[par ^ 1u][i] = 0;
}

// ---------------------------------------------------------------------------
extern "C" void kernel_launch(void* const* d_in, const int* in_sizes, int n_in,
                              void* d_out, int out_size) {
    const float* x   = (const float*)d_in[0];
    const int*   ei  = (const int*)d_in[1];
    const float* W1  = (const float*)d_in[2];
    const float* b1  = (const float*)d_in[3];
    const float* W20 = (const float*)d_in[4];
    const float* W21 = (const float*)d_in[5];
    const float* b2  = (const float*)d_in[6];
    const float* Wl  = (const float*)d_in[7];
    const float* bl  = (const float*)d_in[8];
    float* out = (float*)d_out;

    static cudaStream_t sB = 0;
    static cudaEvent_t e0 = 0, e1 = 0;
    static int init_done = 0;
    if (!init_done) {
        cudaFuncSetAttribute(k_gf2, cudaFuncAttributeMaxDynamicSharedMemorySize, SMEM_F2);
        cudaFuncSetAttribute(k_gemm1, cudaFuncAttributeMaxDynamicSharedMemorySize, G1_SMEM);
        cudaStreamCreateWithFlags(&sB, cudaStreamNonBlocking);
        cudaEventCreateWithFlags(&e0, cudaEventDisableTiming);
        cudaEventCreateWithFlags(&e1, cudaEventDisableTiming);
        init_done = 1;
    }

    // Fork stream B for the graph-independent GEMM1
    cudaEventRecord(e0, 0);
    cudaStreamWaitEvent(sB, e0, 0);
    k_gemm1<<<GRIDN, 256, G1_SMEM, sB>>>(x, W1, b1);
    cudaEventRecord(e1, sB);

    // Stream A: fused hist+fill (single edge pass)
    k_fill<<<GRIDN, 512>>>(ei);

    // Join: gf2 needs h16 (B) + buckets (A)
    cudaStreamWaitEvent(0, e1, 0);
    k_gf2<<<GRIDN, 256, SMEM_F2>>>(W20, W21, b2, Wl, bl, out);
}